// round 4
// baseline (speedup 1.0000x reference)
#include <cuda_runtime.h>
#include <cuda_fp16.h>
#include <math.h>
#include <stdint.h>

// ---------------- problem constants ----------------
#define BATCH   64
#define SEQ     512
#define EDIM    512
#define HDIM    1024
#define VOCAB   32000
#define M0      (BATCH*SEQ)      // 32768 level-0 nodes

// ---------------- device scratch (allocation-free rule) ----------------
// fp16 hi/lo planes for all GEMM operands
__device__ half  g_EMBh[(size_t)VOCAB * EDIM];
__device__ half  g_EMBl[(size_t)VOCAB * EDIM];
__device__ half  g_HB0h[(size_t)M0 * HDIM];
__device__ half  g_HB0l[(size_t)M0 * HDIM];
__device__ half  g_HB1h[(size_t)(M0/2) * HDIM];
__device__ half  g_HB1l[(size_t)(M0/2) * HDIM];
__device__ half  g_RHh [(size_t)(M0/2) * 2 * HDIM];
__device__ half  g_RHl [(size_t)(M0/2) * 2 * HDIM];
__device__ half  g_W0h [(size_t)(2*HDIM) * EDIM];      // [2048][512]  K-major
__device__ half  g_W0l [(size_t)(2*HDIM) * EDIM];
__device__ half  g_UZRh[(size_t)(2*HDIM) * (2*HDIM)];  // [2048][2048]
__device__ half  g_UZRl[(size_t)(2*HDIM) * (2*HDIM)];
__device__ half  g_UHh [(size_t)HDIM * (2*HDIM)];      // [1024][2048]
__device__ half  g_UHl [(size_t)HDIM * (2*HDIM)];
// fp32 scratch
__device__ float g_PRE[(size_t)M0 * 2 * HDIM];         // pre-activations
__device__ float g_Z  [(size_t)(M0/2) * HDIM];         // z gate
__device__ float g_BL0[2*HDIM];                        // [bz_sum | bh_sum]
__device__ float g_BZR[2*HDIM];                        // [bz_sum | br_sum]
__device__ float g_BH [HDIM];                          // bh_sum

// ================= helpers =================
__device__ __forceinline__ uint32_t smem_u32(const void* p) {
    uint32_t a;
    asm("{ .reg .u64 t; cvta.to.shared.u64 t, %1; cvt.u32.u64 %0, t; }" : "=r"(a) : "l"(p));
    return a;
}
__device__ __forceinline__ void split1(float v, half& h, half& l) {
    h = __float2half_rn(v);
    l = __float2half_rn(v - __half2float(h));
}
__device__ __forceinline__ float4 ld4h(const half* p) {   // 8B-aligned
    uint2 u = *(const uint2*)p;
    __half2 a = *(__half2*)&u.x, b = *(__half2*)&u.y;
    float2 fa = __half22float2(a), fb = __half22float2(b);
    return make_float4(fa.x, fa.y, fb.x, fb.y);
}
__device__ __forceinline__ void st4split(half* ph, half* pl, float4 v) {
    half h0, l0, h1, l1, h2, l2, h3, l3;
    split1(v.x, h0, l0); split1(v.y, h1, l1);
    split1(v.z, h2, l2); split1(v.w, h3, l3);
    __half2 H0 = __halves2half2(h0, h1), H1 = __halves2half2(h2, h3);
    __half2 L0 = __halves2half2(l0, l1), L1 = __halves2half2(l2, l3);
    uint2 uh, ul;
    uh.x = *(uint32_t*)&H0; uh.y = *(uint32_t*)&H1;
    ul.x = *(uint32_t*)&L0; ul.y = *(uint32_t*)&L1;
    *(uint2*)ph = uh; *(uint2*)pl = ul;
}

#define CP16(dst, src) asm volatile("cp.async.cg.shared.global [%0], [%1], 16;" :: "r"(dst), "l"(src))
#define CP_COMMIT()    asm volatile("cp.async.commit_group;" ::: "memory")
#define CP_WAIT(n)     asm volatile("cp.async.wait_group %0;" :: "n"(n) : "memory")

#define LDSM4(r0, r1, r2, r3, addr)                                              \
    asm volatile("ldmatrix.sync.aligned.m8n8.x4.shared.b16 {%0,%1,%2,%3}, [%4];" \
        : "=r"(r0), "=r"(r1), "=r"(r2), "=r"(r3) : "r"(addr))

#define MMA16816(d, a, b0, b1)                                                   \
    asm volatile("mma.sync.aligned.m16n8k16.row.col.f32.f16.f16.f32 "            \
        "{%0,%1,%2,%3}, {%4,%5,%6,%7}, {%8,%9}, {%0,%1,%2,%3};"                  \
        : "+f"((d)[0]), "+f"((d)[1]), "+f"((d)[2]), "+f"((d)[3])                  \
        : "r"((a)[0]), "r"((a)[1]), "r"((a)[2]), "r"((a)[3]), "r"(b0), "r"(b1))

// ================= packing kernels =================
// transpose + split: dh/dl[c*dpitch + r] = split(src[r*C + c])
__global__ void transpose_split_kernel(const float* __restrict__ src,
                                       half* __restrict__ dh, half* __restrict__ dl,
                                       int R, int C, int dpitch)
{
    __shared__ float t[32][33];
    int c0 = blockIdx.x * 32, r0 = blockIdx.y * 32;
    int x = threadIdx.x, y = threadIdx.y;   // 32 x 8
    #pragma unroll
    for (int i = 0; i < 32; i += 8) {
        int r = r0 + y + i, c = c0 + x;
        t[y + i][x] = (r < R && c < C) ? src[(size_t)r * C + c] : 0.f;
    }
    __syncthreads();
    #pragma unroll
    for (int i = 0; i < 32; i += 8) {
        int c = c0 + y + i, r = r0 + x;
        if (c < C && r < R) {
            float v = t[x][y + i];
            half h, l; split1(v, h, l);
            dh[(size_t)c * dpitch + r] = h;
            dl[(size_t)c * dpitch + r] = l;
        }
    }
}

__global__ void emb_split_kernel(const float* __restrict__ emb,
                                 half* __restrict__ eh, half* __restrict__ el, int total4)
{
    int q = blockIdx.x * blockDim.x + threadIdx.x;
    if (q >= total4) return;
    int idx = q * 4;
    float4 v = *(const float4*)(emb + idx);
    st4split(eh + idx, el + idx, v);
}

__global__ void bias_kernel(
    const float* __restrict__ bz,  const float* __restrict__ bzl, const float* __restrict__ bzr,
    const float* __restrict__ br,  const float* __restrict__ brl, const float* __restrict__ brr,
    const float* __restrict__ bh,  const float* __restrict__ bhl, const float* __restrict__ bhr)
{
    int i = blockIdx.x * blockDim.x + threadIdx.x;
    if (i >= 1024) return;
    float bzs = bz[i] + bzl[i] + bzr[i];
    float brs = br[i] + brl[i] + brr[i];
    float bhs = bh[i] + bhl[i] + bhr[i];
    g_BZR[i] = bzs; g_BZR[1024 + i] = brs;
    g_BH[i]  = bhs;
    g_BL0[i] = bzs; g_BL0[1024 + i] = bhs;
}

// ================= fp16x3 mma GEMM with cp.async (3-stage) =================
// C(MxN) = (Ah+Al)(MxK) @ (Bh+Bl)(NxK)^T + bias; drop Al*Bl.
// BM=BN=128, BK=32, 256 threads = 8 warps (4m x 2n), warp tile 32x64.
#define BM 128
#define BN 128
#define BK 32
#define PAD_B 80                         // bytes per 32-half row (padded)
#define PLANE_BYTES (128 * PAD_B)        // 10240
#define STAGE_BYTES (4 * PLANE_BYTES)    // 40960
#define NSTAGE 3
#define SMEM_BYTES (NSTAGE * STAGE_BYTES)

template<bool GATHER>
__global__ void __launch_bounds__(256, 1)
gemm_mma_kernel(const half* __restrict__ Ah, const half* __restrict__ Al,
                const int* __restrict__ tok,
                const half* __restrict__ Bh, const half* __restrict__ Bl,
                const float* __restrict__ bias,
                float* __restrict__ C, int M, int N, int K)
{
    extern __shared__ char smem[];
    const uint32_t sb = smem_u32(smem);
    const int tid  = threadIdx.x;
    const int lane = tid & 31;
    const int wid  = tid >> 5;
    const int warp_m = wid & 3;
    const int warp_n = wid >> 2;
    const int bm = blockIdx.y * BM, bn = blockIdx.x * BN;

    // per-thread cp.async mapping: row = tid>>1, 32B segment = (tid&1)*32
    const int arow = tid >> 1;
    const int wb   = (tid & 1) * 32;
    const int gr   = bm + arow;
    const int grc  = (gr < M) ? gr : (M - 1);
    const size_t arowidx = GATHER ? (size_t)__ldg(&tok[grc]) : (size_t)grc;
    const char* pAh = (const char*)(Ah + arowidx * K) + wb;
    const char* pAl = (const char*)(Al + arowidx * K) + wb;
    const char* pBh = (const char*)(Bh + (size_t)(bn + arow) * K) + wb;
    const char* pBl = (const char*)(Bl + (size_t)(bn + arow) * K) + wb;
    const uint32_t so = (uint32_t)(arow * PAD_B + wb);

    auto issue = [&](int s, int kt) {
        const uint32_t d = sb + s * STAGE_BYTES + so;
        const size_t g = (size_t)kt * 64;     // 32 halves = 64 bytes per k-tile row
        CP16(d,                       pAh + g); CP16(d + 16,                   pAh + g + 16);
        CP16(d + PLANE_BYTES,         pAl + g); CP16(d + PLANE_BYTES + 16,     pAl + g + 16);
        CP16(d + 2 * PLANE_BYTES,     pBh + g); CP16(d + 2 * PLANE_BYTES + 16, pBh + g + 16);
        CP16(d + 3 * PLANE_BYTES,     pBl + g); CP16(d + 3 * PLANE_BYTES + 16, pBl + g + 16);
        CP_COMMIT();
    };

    // ldmatrix lane addressing
    const uint32_t a_lane_off = (uint32_t)((warp_m * 32 + (lane & 15)) * PAD_B + ((lane >> 4) * 8) * 2);
    const uint32_t b_lane_off = (uint32_t)((warp_n * 64 + ((lane >> 4) << 3) + (lane & 7)) * PAD_B
                                           + (((lane >> 3) & 1) * 8) * 2);

    float acc[2][8][4];
    #pragma unroll
    for (int mt = 0; mt < 2; mt++)
        #pragma unroll
        for (int t = 0; t < 8; t++)
            #pragma unroll
            for (int j = 0; j < 4; j++) acc[mt][t][j] = 0.f;

    const int NT = K / BK;
    issue(0, 0);
    if (NT > 1) issue(1, 1);

    for (int kt = 0; kt < NT; kt++) {
        if (kt + 1 < NT) { CP_WAIT(1); } else { CP_WAIT(0); }
        __syncthreads();
        if (kt + 2 < NT) issue((kt + 2) % NSTAGE, kt + 2);

        const uint32_t sbase = sb + (kt % NSTAGE) * STAGE_BYTES;
        #pragma unroll
        for (int ks = 0; ks < 2; ks++) {
            const uint32_t koff = ks * 32;  // 16 halves * 2B
            uint32_t ah[2][4], al[2][4], bh[4][4], bl[4][4];
            #pragma unroll
            for (int mt = 0; mt < 2; mt++) {
                uint32_t ad = sbase + a_lane_off + mt * (16 * PAD_B) + koff;
                LDSM4(ah[mt][0], ah[mt][1], ah[mt][2], ah[mt][3], ad);
                LDSM4(al[mt][0], al[mt][1], al[mt][2], al[mt][3], ad + PLANE_BYTES);
            }
            #pragma unroll
            for (int ng = 0; ng < 4; ng++) {
                uint32_t bd = sbase + 2 * PLANE_BYTES + b_lane_off + ng * (16 * PAD_B) + koff;
                LDSM4(bh[ng][0], bh[ng][1], bh[ng][2], bh[ng][3], bd);
                LDSM4(bl[ng][0], bl[ng][1], bl[ng][2], bl[ng][3], bd + PLANE_BYTES);
            }
            #pragma unroll
            for (int mt = 0; mt < 2; mt++)
                #pragma unroll
                for (int ng = 0; ng < 4; ng++)
                    #pragma unroll
                    for (int p = 0; p < 2; p++) {
                        float* c = acc[mt][ng * 2 + p];
                        MMA16816(c, ah[mt], bh[ng][2 * p], bh[ng][2 * p + 1]);
                        MMA16816(c, ah[mt], bl[ng][2 * p], bl[ng][2 * p + 1]);
                        MMA16816(c, al[mt], bh[ng][2 * p], bh[ng][2 * p + 1]);
                    }
        }
        __syncthreads();
    }

    // epilogue: fragment -> gmem with bias
    const int r0 = bm + warp_m * 32 + (lane >> 2);
    const int c0 = bn + warp_n * 64 + (lane & 3) * 2;
    #pragma unroll
    for (int mt = 0; mt < 2; mt++) {
        const int row = r0 + mt * 16;
        #pragma unroll
        for (int t = 0; t < 8; t++) {
            const int col = c0 + t * 8;
            const float b0 = bias[col], b1 = bias[col + 1];
            if (row < M) {
                float2 v = make_float2(acc[mt][t][0] + b0, acc[mt][t][1] + b1);
                *(float2*)(C + (size_t)row * N + col) = v;
            }
            if (row + 8 < M) {
                float2 v = make_float2(acc[mt][t][2] + b0, acc[mt][t][3] + b1);
                *(float2*)(C + (size_t)(row + 8) * N + col) = v;
            }
        }
    }
}

// ================= elementwise epilogues (float4, split outputs) =================
__device__ __forceinline__ float sigmf(float x) { return 1.f / (1.f + expf(-x)); }

// level 0: pre = [zpre | hpre] (M x 2048) -> h0 = (1-z)*tanh(hpre) -> hi/lo planes
__global__ void e0_kernel(const float* __restrict__ pre,
                          half* __restrict__ hh, half* __restrict__ hl, int total4)
{
    int q = blockIdx.x * blockDim.x + threadIdx.x;
    if (q >= total4) return;
    int idx = q * 4;
    int m = idx >> 10, j = idx & 1023;
    size_t o = (size_t)m * 2048 + j;
    float4 zp = *(const float4*)(pre + o);
    float4 hp = *(const float4*)(pre + o + 1024);
    float4 r;
    r.x = (1.f - sigmf(zp.x)) * tanhf(hp.x);
    r.y = (1.f - sigmf(zp.y)) * tanhf(hp.y);
    r.z = (1.f - sigmf(zp.z)) * tanhf(hp.z);
    r.w = (1.f - sigmf(zp.w)) * tanhf(hp.w);
    st4split(hh + idx, hl + idx, r);
}

// after GEMM1: pre = [zpre | rpre]; hprev planes viewed (M,2048) = [hl|hr]
__global__ void e1_kernel(const float* __restrict__ pre,
                          const half* __restrict__ hph, const half* __restrict__ hpl,
                          float* __restrict__ zb,
                          half* __restrict__ rhh, half* __restrict__ rhl, int total4)
{
    int q = blockIdx.x * blockDim.x + threadIdx.x;
    if (q >= total4) return;
    int idx = q * 4;
    int m = idx >> 10, j = idx & 1023;
    size_t o = (size_t)m * 2048 + j;
    float4 zp = *(const float4*)(pre + o);
    float4 rp = *(const float4*)(pre + o + 1024);
    float4 Hh = ld4h(hph + o),        Lh = ld4h(hpl + o);
    float4 Hr = ld4h(hph + o + 1024), Lr = ld4h(hpl + o + 1024);
    float hlx = Hh.x + Lh.x, hly = Hh.y + Lh.y, hlz = Hh.z + Lh.z, hlw = Hh.w + Lh.w;
    float hrx = Hr.x + Lr.x, hry = Hr.y + Lr.y, hrz = Hr.z + Lr.z, hrw = Hr.w + Lr.w;
    float4 z;
    z.x = sigmf(zp.x); z.y = sigmf(zp.y); z.z = sigmf(zp.z); z.w = sigmf(zp.w);
    float rx = sigmf(rp.x), ry = sigmf(rp.y), rz = sigmf(rp.z), rw = sigmf(rp.w);
    *(float4*)(zb + idx) = z;
    st4split(rhh + o,        rhl + o,        make_float4(rx * hlx, ry * hly, rz * hlz, rw * hlw));
    st4split(rhh + o + 1024, rhl + o + 1024, make_float4(rx * hrx, ry * hry, rz * hrz, rw * hrw));
}

// after GEMM2: h = z*(hl+hr) + (1-z)*tanh(pre2)
template<bool FINAL>
__global__ void e2_kernel(const float* __restrict__ pre2, const float* __restrict__ zb,
                          const half* __restrict__ hph, const half* __restrict__ hpl,
                          half* __restrict__ hoh, half* __restrict__ hol,
                          float* __restrict__ outf, int total4)
{
    int q = blockIdx.x * blockDim.x + threadIdx.x;
    if (q >= total4) return;
    int idx = q * 4;
    int m = idx >> 10, j = idx & 1023;
    size_t o = (size_t)m * 2048 + j;
    float4 z  = *(const float4*)(zb + idx);
    float4 p  = *(const float4*)(pre2 + idx);
    float4 Hh = ld4h(hph + o),        Lh = ld4h(hpl + o);
    float4 Hr = ld4h(hph + o + 1024), Lr = ld4h(hpl + o + 1024);
    float4 r;
    r.x = z.x * ((Hh.x + Lh.x) + (Hr.x + Lr.x)) + (1.f - z.x) * tanhf(p.x);
    r.y = z.y * ((Hh.y + Lh.y) + (Hr.y + Lr.y)) + (1.f - z.y) * tanhf(p.y);
    r.z = z.z * ((Hh.z + Lh.z) + (Hr.z + Lr.z)) + (1.f - z.z) * tanhf(p.z);
    r.w = z.w * ((Hh.w + Lh.w) + (Hr.w + Lr.w)) + (1.f - z.w) * tanhf(p.w);
    if (FINAL) *(float4*)(outf + idx) = r;
    else       st4split(hoh + idx, hol + idx, r);
}

// ================= launch =================
extern "C" void kernel_launch(void* const* d_in, const int* in_sizes, int n_in,
                              void* d_out, int out_size)
{
    const int*   tokens = (const int*)  d_in[0];
    const float* emb    = (const float*)d_in[1];
    const float* W_z  = (const float*)d_in[2];
    const float* b_z  = (const float*)d_in[3];
    const float* U_zl = (const float*)d_in[4];
    const float* b_zl = (const float*)d_in[5];
    const float* U_zr = (const float*)d_in[6];
    const float* b_zr = (const float*)d_in[7];
    const float* W_r  = (const float*)d_in[8];
    const float* b_r  = (const float*)d_in[9];
    const float* U_rl = (const float*)d_in[10];
    const float* b_rl = (const float*)d_in[11];
    const float* U_rr = (const float*)d_in[12];
    const float* b_rr = (const float*)d_in[13];
    const float* W_h  = (const float*)d_in[14];
    const float* b_h  = (const float*)d_in[15];
    const float* U_hl = (const float*)d_in[16];
    const float* b_hl = (const float*)d_in[17];
    const float* U_hr = (const float*)d_in[18];
    const float* b_hr = (const float*)d_in[19];
    (void)W_r; // level-0 r is multiplied by hl=hr=0

    half *EMBh, *EMBl, *HB0h, *HB0l, *HB1h, *HB1l, *RHh, *RHl;
    half *W0h, *W0l, *UZRh, *UZRl, *UHh, *UHl;
    float *PRE, *ZB, *BL0, *BZR, *BH;
    cudaGetSymbolAddress((void**)&EMBh, g_EMBh);
    cudaGetSymbolAddress((void**)&EMBl, g_EMBl);
    cudaGetSymbolAddress((void**)&HB0h, g_HB0h);
    cudaGetSymbolAddress((void**)&HB0l, g_HB0l);
    cudaGetSymbolAddress((void**)&HB1h, g_HB1h);
    cudaGetSymbolAddress((void**)&HB1l, g_HB1l);
    cudaGetSymbolAddress((void**)&RHh,  g_RHh);
    cudaGetSymbolAddress((void**)&RHl,  g_RHl);
    cudaGetSymbolAddress((void**)&W0h,  g_W0h);
    cudaGetSymbolAddress((void**)&W0l,  g_W0l);
    cudaGetSymbolAddress((void**)&UZRh, g_UZRh);
    cudaGetSymbolAddress((void**)&UZRl, g_UZRl);
    cudaGetSymbolAddress((void**)&UHh,  g_UHh);
    cudaGetSymbolAddress((void**)&UHl,  g_UHl);
    cudaGetSymbolAddress((void**)&PRE,  g_PRE);
    cudaGetSymbolAddress((void**)&ZB,   g_Z);
    cudaGetSymbolAddress((void**)&BL0,  g_BL0);
    cudaGetSymbolAddress((void**)&BZR,  g_BZR);
    cudaGetSymbolAddress((void**)&BH,   g_BH);

    cudaFuncSetAttribute(gemm_mma_kernel<true>,
                         cudaFuncAttributeMaxDynamicSharedMemorySize, SMEM_BYTES);
    cudaFuncSetAttribute(gemm_mma_kernel<false>,
                         cudaFuncAttributeMaxDynamicSharedMemorySize, SMEM_BYTES);

    // ---- pack: transpose+split weights into [N][K] hi/lo half planes ----
    {
        dim3 blk(32, 8);
        dim3 g32(1024 / 32, 1024 / 32);
        transpose_split_kernel<<<g32, blk>>>(U_zl, UZRh, UZRl,                                 1024, 1024, 2048);
        transpose_split_kernel<<<g32, blk>>>(U_rl, UZRh + (size_t)1024*2048, UZRl + (size_t)1024*2048, 1024, 1024, 2048);
        transpose_split_kernel<<<g32, blk>>>(U_zr, UZRh + 1024, UZRl + 1024,                   1024, 1024, 2048);
        transpose_split_kernel<<<g32, blk>>>(U_rr, UZRh + (size_t)1024*2048 + 1024, UZRl + (size_t)1024*2048 + 1024, 1024, 1024, 2048);
        transpose_split_kernel<<<g32, blk>>>(U_hl, UHh, UHl,               1024, 1024, 2048);
        transpose_split_kernel<<<g32, blk>>>(U_hr, UHh + 1024, UHl + 1024, 1024, 1024, 2048);
        dim3 gW(1024 / 32, 512 / 32);
        transpose_split_kernel<<<gW, blk>>>(W_z, W0h, W0l,                                         512, 1024, 512);
        transpose_split_kernel<<<gW, blk>>>(W_h, W0h + (size_t)1024*512, W0l + (size_t)1024*512,   512, 1024, 512);
        int etotal4 = VOCAB * EDIM / 4;
        emb_split_kernel<<<(etotal4 + 255) / 256, 256>>>(emb, EMBh, EMBl, etotal4);
        bias_kernel<<<4, 256>>>(b_z, b_zl, b_zr, b_r, b_rl, b_rr, b_h, b_hl, b_hr);
    }

    // ---- level 0 ----
    {
        dim3 grid(2 * HDIM / BN, M0 / BM);
        gemm_mma_kernel<true><<<grid, 256, SMEM_BYTES>>>(EMBh, EMBl, tokens, W0h, W0l, BL0, PRE,
                                                         M0, 2 * HDIM, EDIM);
        int total4 = M0 * HDIM / 4;
        e0_kernel<<<(total4 + 255) / 256, 256>>>(PRE, HB0h, HB0l, total4);
    }

    // ---- tree levels: n = 512 -> 1 ----
    half* hph = HB0h; half* hpl = HB0l;
    int n = SEQ, lvl = 0;
    while (n > 1) {
        int Mn = BATCH * (n / 2);
        bool final = (n / 2 == 1);
        half* hoh = (lvl & 1) ? HB0h : HB1h;
        half* hol = (lvl & 1) ? HB0l : HB1l;
        int gy = (Mn + BM - 1) / BM;
        int total4 = Mn * HDIM / 4;

        // GEMM1: [hl|hr](Mn x 2048) @ UZR + [bz|br]
        {
            dim3 grid(2 * HDIM / BN, gy);
            gemm_mma_kernel<false><<<grid, 256, SMEM_BYTES>>>(hph, hpl, nullptr, UZRh, UZRl, BZR, PRE,
                                                              Mn, 2 * HDIM, 2 * HDIM);
        }
        e1_kernel<<<(total4 + 255) / 256, 256>>>(PRE, hph, hpl, ZB, RHh, RHl, total4);
        // GEMM2: [r*hl|r*hr](Mn x 2048) @ UH + bh
        {
            dim3 grid(HDIM / BN, gy);
            gemm_mma_kernel<false><<<grid, 256, SMEM_BYTES>>>(RHh, RHl, nullptr, UHh, UHl, BH, PRE,
                                                              Mn, HDIM, 2 * HDIM);
        }
        if (final)
            e2_kernel<true><<<(total4 + 255) / 256, 256>>>(PRE, ZB, hph, hpl, nullptr, nullptr,
                                                           (float*)d_out, total4);
        else
            e2_kernel<false><<<(total4 + 255) / 256, 256>>>(PRE, ZB, hph, hpl, hoh, hol,
                                                            nullptr, total4);

        hph = hoh; hpl = hol;
        n /= 2;
        lvl++;
    }
    (void)in_sizes; (void)n_in; (void)out_size;
}

// round 7
// speedup vs baseline: 1.2005x; 1.2005x over previous
#include <cuda_runtime.h>
#include <cuda_fp16.h>
#include <math.h>
#include <stdint.h>

// ---------------- problem constants ----------------
#define BATCH   64
#define SEQ     512
#define EDIM    512
#define HDIM    1024
#define VOCAB   32000
#define M0      (BATCH*SEQ)      // 32768 level-0 nodes

// ---------------- device scratch (allocation-free rule) ----------------
// fp16 hi/lo planes for all GEMM operands
__device__ half  g_EMBh[(size_t)VOCAB * EDIM];
__device__ half  g_EMBl[(size_t)VOCAB * EDIM];
__device__ half  g_HB0h[(size_t)M0 * HDIM];
__device__ half  g_HB0l[(size_t)M0 * HDIM];
__device__ half  g_HB1h[(size_t)(M0/2) * HDIM];
__device__ half  g_HB1l[(size_t)(M0/2) * HDIM];
__device__ half  g_RHh [(size_t)(M0/2) * 2 * HDIM];
__device__ half  g_RHl [(size_t)(M0/2) * 2 * HDIM];
__device__ half  g_W0h [(size_t)(2*HDIM) * EDIM];      // [2048][512]  K-major
__device__ half  g_W0l [(size_t)(2*HDIM) * EDIM];
__device__ half  g_UZRh[(size_t)(2*HDIM) * (2*HDIM)];  // [2048][2048]
__device__ half  g_UZRl[(size_t)(2*HDIM) * (2*HDIM)];
__device__ half  g_UHh [(size_t)HDIM * (2*HDIM)];      // [1024][2048]
__device__ half  g_UHl [(size_t)HDIM * (2*HDIM)];
// fp32 scratch
__device__ float g_PRE[(size_t)M0 * 2 * HDIM];         // pre-activations
__device__ float g_Z  [(size_t)(M0/2) * HDIM];         // z gate
__device__ float g_BL0[2*HDIM];                        // [bz_sum | bh_sum]
__device__ float g_BZR[2*HDIM];                        // [bz_sum | br_sum]
__device__ float g_BH [HDIM];                          // bh_sum

// ================= helpers =================
__device__ __forceinline__ uint32_t smem_u32(const void* p) {
    uint32_t a;
    asm("{ .reg .u64 t; cvta.to.shared.u64 t, %1; cvt.u32.u64 %0, t; }" : "=r"(a) : "l"(p));
    return a;
}
__device__ __forceinline__ void split1(float v, half& h, half& l) {
    h = __float2half_rn(v);
    l = __float2half_rn(v - __half2float(h));
}
__device__ __forceinline__ float4 ld4h(const half* p) {   // 8B-aligned
    uint2 u = *(const uint2*)p;
    __half2 a = *(__half2*)&u.x, b = *(__half2*)&u.y;
    float2 fa = __half22float2(a), fb = __half22float2(b);
    return make_float4(fa.x, fa.y, fb.x, fb.y);
}
__device__ __forceinline__ void st4split(half* ph, half* pl, float4 v) {
    half h0, l0, h1, l1, h2, l2, h3, l3;
    split1(v.x, h0, l0); split1(v.y, h1, l1);
    split1(v.z, h2, l2); split1(v.w, h3, l3);
    __half2 H0 = __halves2half2(h0, h1), H1 = __halves2half2(h2, h3);
    __half2 L0 = __halves2half2(l0, l1), L1 = __halves2half2(l2, l3);
    uint2 uh, ul;
    uh.x = *(uint32_t*)&H0; uh.y = *(uint32_t*)&H1;
    ul.x = *(uint32_t*)&L0; ul.y = *(uint32_t*)&L1;
    *(uint2*)ph = uh; *(uint2*)pl = ul;
}

#define LDSM4(r0, r1, r2, r3, addr)                                              \
    asm volatile("ldmatrix.sync.aligned.m8n8.x4.shared.b16 {%0,%1,%2,%3}, [%4];" \
        : "=r"(r0), "=r"(r1), "=r"(r2), "=r"(r3) : "r"(addr))

#define MMA16816(d, a, b0, b1)                                                   \
    asm volatile("mma.sync.aligned.m16n8k16.row.col.f32.f16.f16.f32 "            \
        "{%0,%1,%2,%3}, {%4,%5,%6,%7}, {%8,%9}, {%0,%1,%2,%3};"                  \
        : "+f"((d)[0]), "+f"((d)[1]), "+f"((d)[2]), "+f"((d)[3])                  \
        : "r"((a)[0]), "r"((a)[1]), "r"((a)[2]), "r"((a)[3]), "r"(b0), "r"(b1))

// ================= packing kernels =================
// transpose + split: dh/dl[c*dpitch + r] = split(src[r*C + c])
__global__ void transpose_split_kernel(const float* __restrict__ src,
                                       half* __restrict__ dh, half* __restrict__ dl,
                                       int R, int C, int dpitch)
{
    __shared__ float t[32][33];
    int c0 = blockIdx.x * 32, r0 = blockIdx.y * 32;
    int x = threadIdx.x, y = threadIdx.y;   // 32 x 8
    #pragma unroll
    for (int i = 0; i < 32; i += 8) {
        int r = r0 + y + i, c = c0 + x;
        t[y + i][x] = (r < R && c < C) ? src[(size_t)r * C + c] : 0.f;
    }
    __syncthreads();
    #pragma unroll
    for (int i = 0; i < 32; i += 8) {
        int c = c0 + y + i, r = r0 + x;
        if (c < C && r < R) {
            float v = t[x][y + i];
            half h, l; split1(v, h, l);
            dh[(size_t)c * dpitch + r] = h;
            dl[(size_t)c * dpitch + r] = l;
        }
    }
}

__global__ void emb_split_kernel(const float* __restrict__ emb,
                                 half* __restrict__ eh, half* __restrict__ el, int total4)
{
    int q = blockIdx.x * blockDim.x + threadIdx.x;
    if (q >= total4) return;
    int idx = q * 4;
    float4 v = *(const float4*)(emb + idx);
    st4split(eh + idx, el + idx, v);
}

__global__ void bias_kernel(
    const float* __restrict__ bz,  const float* __restrict__ bzl, const float* __restrict__ bzr,
    const float* __restrict__ br,  const float* __restrict__ brl, const float* __restrict__ brr,
    const float* __restrict__ bh,  const float* __restrict__ bhl, const float* __restrict__ bhr)
{
    int i = blockIdx.x * blockDim.x + threadIdx.x;
    if (i >= 1024) return;
    float bzs = bz[i] + bzl[i] + bzr[i];
    float brs = br[i] + brl[i] + brr[i];
    float bhs = bh[i] + bhl[i] + bhr[i];
    g_BZR[i] = bzs; g_BZR[1024 + i] = brs;
    g_BH[i]  = bhs;
    g_BL0[i] = bzs; g_BL0[1024 + i] = bhs;
}

// ================= fp16x3 mma GEMM, register-staged double buffer =================
// C(MxN) = (Ah+Al)(MxK) @ (Bh+Bl)(NxK)^T + bias; drop Al*Bl.
// BM=BN=128, BK=32, 256 threads = 8 warps (4m x 2n), warp tile 32x64.
#define BM 128
#define BN 128
#define BK 32
#define PAD_B 80                         // bytes per 32-half row (padded)
#define PLANE_BYTES (128 * PAD_B)        // 10240
#define STAGE_BYTES (4 * PLANE_BYTES)    // 40960: [Ah|Al|Bh|Bl]
#define SMEM_BYTES  (2 * STAGE_BYTES)    // 81920

template<bool GATHER>
__global__ void __launch_bounds__(256, 1)
gemm_mma_kernel(const half* __restrict__ Ah, const half* __restrict__ Al,
                const int* __restrict__ tok,
                const half* __restrict__ Bh, const half* __restrict__ Bl,
                const float* __restrict__ bias,
                float* __restrict__ C, int M, int N, int K)
{
    extern __shared__ char smem[];
    const uint32_t sb = smem_u32(smem);
    const int tid  = threadIdx.x;
    const int lane = tid & 31;
    const int wid  = tid >> 5;
    const int warp_m = wid & 3;
    const int warp_n = wid >> 2;
    const int bm = blockIdx.y * BM, bn = blockIdx.x * BN;

    // per-thread staging: 2 (row,16B-seg) slots per plane; plane rows are 64 B (4 segs).
    // slot i covers idx = tid + 256*i over (row = idx>>2, seg = idx&3).
    const char* pA_h[2]; const char* pA_l[2]; const char* pB_h[2]; const char* pB_l[2];
    uint32_t soff[2]; bool okA[2];
    #pragma unroll
    for (int i = 0; i < 2; i++) {
        int idx = tid + 256 * i;        // 0..511
        int row = idx >> 2;             // 0..127
        int seg = (idx & 3) * 16;       // byte offset within 64B row
        soff[i] = (uint32_t)(row * PAD_B + seg);
        int gr = bm + row;
        okA[i] = gr < M;
        int grc = okA[i] ? gr : 0;
        size_t ar = GATHER ? (size_t)__ldg(&tok[grc]) : (size_t)grc;
        pA_h[i] = (const char*)(Ah + ar * K) + seg;
        pA_l[i] = (const char*)(Al + ar * K) + seg;
        pB_h[i] = (const char*)(Bh + (size_t)(bn + row) * K) + seg;
        pB_l[i] = (const char*)(Bl + (size_t)(bn + row) * K) + seg;
    }

    uint4 rAh[2], rAl[2], rBh[2], rBl[2];
    const uint4 z4 = make_uint4(0, 0, 0, 0);
    auto loadRegs = [&](int kt) {
        const size_t g = (size_t)kt * 64;   // 32 halves = 64 B per k-tile
        #pragma unroll
        for (int i = 0; i < 2; i++) {
            rAh[i] = okA[i] ? *(const uint4*)(pA_h[i] + g) : z4;
            rAl[i] = okA[i] ? *(const uint4*)(pA_l[i] + g) : z4;
            rBh[i] = *(const uint4*)(pB_h[i] + g);
            rBl[i] = *(const uint4*)(pB_l[i] + g);
        }
    };
    auto storeShared = [&](int buf) {
        char* base = smem + buf * STAGE_BYTES;
        #pragma unroll
        for (int i = 0; i < 2; i++) {
            *(uint4*)(base +                   soff[i]) = rAh[i];
            *(uint4*)(base + PLANE_BYTES     + soff[i]) = rAl[i];
            *(uint4*)(base + 2 * PLANE_BYTES + soff[i]) = rBh[i];
            *(uint4*)(base + 3 * PLANE_BYTES + soff[i]) = rBl[i];
        }
    };

    // ldmatrix lane addressing
    const uint32_t a_lane_off = (uint32_t)((warp_m * 32 + (lane & 15)) * PAD_B + ((lane >> 4) * 8) * 2);
    const uint32_t b_lane_off = (uint32_t)((warp_n * 64 + ((lane >> 4) << 3) + (lane & 7)) * PAD_B
                                           + (((lane >> 3) & 1) * 8) * 2);

    float acc[2][8][4];
    #pragma unroll
    for (int mt = 0; mt < 2; mt++)
        #pragma unroll
        for (int t = 0; t < 8; t++)
            #pragma unroll
            for (int j = 0; j < 4; j++) acc[mt][t][j] = 0.f;

    const int NT = K / BK;
    loadRegs(0);
    storeShared(0);
    __syncthreads();

    for (int kt = 0; kt < NT; kt++) {
        const int buf = kt & 1;
        if (kt + 1 < NT) loadRegs(kt + 1);

        const uint32_t sbase = sb + buf * STAGE_BYTES;
        #pragma unroll
        for (int ks = 0; ks < 2; ks++) {
            const uint32_t koff = ks * 32;  // 16 halves * 2B
            uint32_t ah[2][4], al[2][4], bh[4][4], bl[4][4];
            #pragma unroll
            for (int mt = 0; mt < 2; mt++) {
                uint32_t ad = sbase + a_lane_off + mt * (16 * PAD_B) + koff;
                LDSM4(ah[mt][0], ah[mt][1], ah[mt][2], ah[mt][3], ad);
                LDSM4(al[mt][0], al[mt][1], al[mt][2], al[mt][3], ad + PLANE_BYTES);
            }
            #pragma unroll
            for (int ng = 0; ng < 4; ng++) {
                uint32_t bd = sbase + 2 * PLANE_BYTES + b_lane_off + ng * (16 * PAD_B) + koff;
                LDSM4(bh[ng][0], bh[ng][1], bh[ng][2], bh[ng][3], bd);
                LDSM4(bl[ng][0], bl[ng][1], bl[ng][2], bl[ng][3], bd + PLANE_BYTES);
            }
            #pragma unroll
            for (int mt = 0; mt < 2; mt++)
                #pragma unroll
                for (int ng = 0; ng < 4; ng++)
                    #pragma unroll
                    for (int p = 0; p < 2; p++) {
                        float* c = acc[mt][ng * 2 + p];
                        MMA16816(c, ah[mt], bh[ng][2 * p], bh[ng][2 * p + 1]);
                        MMA16816(c, ah[mt], bl[ng][2 * p], bl[ng][2 * p + 1]);
                        MMA16816(c, al[mt], bh[ng][2 * p], bh[ng][2 * p + 1]);
                    }
        }

        if (kt + 1 < NT) {
            storeShared(buf ^ 1);
            __syncthreads();
        }
    }

    // epilogue: fragment -> gmem with bias
    const int r0 = bm + warp_m * 32 + (lane >> 2);
    const int c0 = bn + warp_n * 64 + (lane & 3) * 2;
    #pragma unroll
    for (int mt = 0; mt < 2; mt++) {
        const int row = r0 + mt * 16;
        #pragma unroll
        for (int t = 0; t < 8; t++) {
            const int col = c0 + t * 8;
            const float b0 = bias[col], b1 = bias[col + 1];
            if (row < M) {
                float2 v = make_float2(acc[mt][t][0] + b0, acc[mt][t][1] + b1);
                *(float2*)(C + (size_t)row * N + col) = v;
            }
            if (row + 8 < M) {
                float2 v = make_float2(acc[mt][t][2] + b0, acc[mt][t][3] + b1);
                *(float2*)(C + (size_t)(row + 8) * N + col) = v;
            }
        }
    }
}

// ================= elementwise epilogues (float4, split outputs) =================
__device__ __forceinline__ float sigmf(float x) { return 1.f / (1.f + expf(-x)); }

// level 0: pre = [zpre | hpre] (M x 2048) -> h0 = (1-z)*tanh(hpre) -> hi/lo planes
__global__ void e0_kernel(const float* __restrict__ pre,
                          half* __restrict__ hh, half* __restrict__ hl, int total4)
{
    int q = blockIdx.x * blockDim.x + threadIdx.x;
    if (q >= total4) return;
    int idx = q * 4;
    int m = idx >> 10, j = idx & 1023;
    size_t o = (size_t)m * 2048 + j;
    float4 zp = *(const float4*)(pre + o);
    float4 hp = *(const float4*)(pre + o + 1024);
    float4 r;
    r.x = (1.f - sigmf(zp.x)) * tanhf(hp.x);
    r.y = (1.f - sigmf(zp.y)) * tanhf(hp.y);
    r.z = (1.f - sigmf(zp.z)) * tanhf(hp.z);
    r.w = (1.f - sigmf(zp.w)) * tanhf(hp.w);
    st4split(hh + idx, hl + idx, r);
}

// after GEMM1: pre = [zpre | rpre]; hprev planes viewed (M,2048) = [hl|hr]
__global__ void e1_kernel(const float* __restrict__ pre,
                          const half* __restrict__ hph, const half* __restrict__ hpl,
                          float* __restrict__ zb,
                          half* __restrict__ rhh, half* __restrict__ rhl, int total4)
{
    int q = blockIdx.x * blockDim.x + threadIdx.x;
    if (q >= total4) return;
    int idx = q * 4;
    int m = idx >> 10, j = idx & 1023;
    size_t o = (size_t)m * 2048 + j;
    float4 zp = *(const float4*)(pre + o);
    float4 rp = *(const float4*)(pre + o + 1024);
    float4 Hh = ld4h(hph + o),        Lh = ld4h(hpl + o);
    float4 Hr = ld4h(hph + o + 1024), Lr = ld4h(hpl + o + 1024);
    float hlx = Hh.x + Lh.x, hly = Hh.y + Lh.y, hlz = Hh.z + Lh.z, hlw = Hh.w + Lh.w;
    float hrx = Hr.x + Lr.x, hry = Hr.y + Lr.y, hrz = Hr.z + Lr.z, hrw = Hr.w + Lr.w;
    float4 z;
    z.x = sigmf(zp.x); z.y = sigmf(zp.y); z.z = sigmf(zp.z); z.w = sigmf(zp.w);
    float rx = sigmf(rp.x), ry = sigmf(rp.y), rz = sigmf(rp.z), rw = sigmf(rp.w);
    *(float4*)(zb + idx) = z;
    st4split(rhh + o,        rhl + o,        make_float4(rx * hlx, ry * hly, rz * hlz, rw * hlw));
    st4split(rhh + o + 1024, rhl + o + 1024, make_float4(rx * hrx, ry * hry, rz * hrz, rw * hrw));
}

// after GEMM2: h = z*(hl+hr) + (1-z)*tanh(pre2)
template<bool FINAL>
__global__ void e2_kernel(const float* __restrict__ pre2, const float* __restrict__ zb,
                          const half* __restrict__ hph, const half* __restrict__ hpl,
                          half* __restrict__ hoh, half* __restrict__ hol,
                          float* __restrict__ outf, int total4)
{
    int q = blockIdx.x * blockDim.x + threadIdx.x;
    if (q >= total4) return;
    int idx = q * 4;
    int m = idx >> 10, j = idx & 1023;
    size_t o = (size_t)m * 2048 + j;
    float4 z  = *(const float4*)(zb + idx);
    float4 p  = *(const float4*)(pre2 + idx);
    float4 Hh = ld4h(hph + o),        Lh = ld4h(hpl + o);
    float4 Hr = ld4h(hph + o + 1024), Lr = ld4h(hpl + o + 1024);
    float4 r;
    r.x = z.x * ((Hh.x + Lh.x) + (Hr.x + Lr.x)) + (1.f - z.x) * tanhf(p.x);
    r.y = z.y * ((Hh.y + Lh.y) + (Hr.y + Lr.y)) + (1.f - z.y) * tanhf(p.y);
    r.z = z.z * ((Hh.z + Lh.z) + (Hr.z + Lr.z)) + (1.f - z.z) * tanhf(p.z);
    r.w = z.w * ((Hh.w + Lh.w) + (Hr.w + Lr.w)) + (1.f - z.w) * tanhf(p.w);
    if (FINAL) *(float4*)(outf + idx) = r;
    else       st4split(hoh + idx, hol + idx, r);
}

// ================= launch =================
extern "C" void kernel_launch(void* const* d_in, const int* in_sizes, int n_in,
                              void* d_out, int out_size)
{
    const int*   tokens = (const int*)  d_in[0];
    const float* emb    = (const float*)d_in[1];
    const float* W_z  = (const float*)d_in[2];
    const float* b_z  = (const float*)d_in[3];
    const float* U_zl = (const float*)d_in[4];
    const float* b_zl = (const float*)d_in[5];
    const float* U_zr = (const float*)d_in[6];
    const float* b_zr = (const float*)d_in[7];
    const float* W_r  = (const float*)d_in[8];
    const float* b_r  = (const float*)d_in[9];
    const float* U_rl = (const float*)d_in[10];
    const float* b_rl = (const float*)d_in[11];
    const float* U_rr = (const float*)d_in[12];
    const float* b_rr = (const float*)d_in[13];
    const float* W_h  = (const float*)d_in[14];
    const float* b_h  = (const float*)d_in[15];
    const float* U_hl = (const float*)d_in[16];
    const float* b_hl = (const float*)d_in[17];
    const float* U_hr = (const float*)d_in[18];
    const float* b_hr = (const float*)d_in[19];
    (void)W_r; // level-0 r is multiplied by hl=hr=0

    half *EMBh, *EMBl, *HB0h, *HB0l, *HB1h, *HB1l, *RHh, *RHl;
    half *W0h, *W0l, *UZRh, *UZRl, *UHh, *UHl;
    float *PRE, *ZB, *BL0, *BZR, *BH;
    cudaGetSymbolAddress((void**)&EMBh, g_EMBh);
    cudaGetSymbolAddress((void**)&EMBl, g_EMBl);
    cudaGetSymbolAddress((void**)&HB0h, g_HB0h);
    cudaGetSymbolAddress((void**)&HB0l, g_HB0l);
    cudaGetSymbolAddress((void**)&HB1h, g_HB1h);
    cudaGetSymbolAddress((void**)&HB1l, g_HB1l);
    cudaGetSymbolAddress((void**)&RHh,  g_RHh);
    cudaGetSymbolAddress((void**)&RHl,  g_RHl);
    cudaGetSymbolAddress((void**)&W0h,  g_W0h);
    cudaGetSymbolAddress((void**)&W0l,  g_W0l);
    cudaGetSymbolAddress((void**)&UZRh, g_UZRh);
    cudaGetSymbolAddress((void**)&UZRl, g_UZRl);
    cudaGetSymbolAddress((void**)&UHh,  g_UHh);
    cudaGetSymbolAddress((void**)&UHl,  g_UHl);
    cudaGetSymbolAddress((void**)&PRE,  g_PRE);
    cudaGetSymbolAddress((void**)&ZB,   g_Z);
    cudaGetSymbolAddress((void**)&BL0,  g_BL0);
    cudaGetSymbolAddress((void**)&BZR,  g_BZR);
    cudaGetSymbolAddress((void**)&BH,   g_BH);

    cudaFuncSetAttribute(gemm_mma_kernel<true>,
                         cudaFuncAttributeMaxDynamicSharedMemorySize, SMEM_BYTES);
    cudaFuncSetAttribute(gemm_mma_kernel<false>,
                         cudaFuncAttributeMaxDynamicSharedMemorySize, SMEM_BYTES);

    // ---- pack: transpose+split weights into [N][K] hi/lo half planes ----
    {
        dim3 blk(32, 8);
        dim3 g32(1024 / 32, 1024 / 32);
        transpose_split_kernel<<<g32, blk>>>(U_zl, UZRh, UZRl,                                 1024, 1024, 2048);
        transpose_split_kernel<<<g32, blk>>>(U_rl, UZRh + (size_t)1024*2048, UZRl + (size_t)1024*2048, 1024, 1024, 2048);
        transpose_split_kernel<<<g32, blk>>>(U_zr, UZRh + 1024, UZRl + 1024,                   1024, 1024, 2048);
        transpose_split_kernel<<<g32, blk>>>(U_rr, UZRh + (size_t)1024*2048 + 1024, UZRl + (size_t)1024*2048 + 1024, 1024, 1024, 2048);
        transpose_split_kernel<<<g32, blk>>>(U_hl, UHh, UHl,               1024, 1024, 2048);
        transpose_split_kernel<<<g32, blk>>>(U_hr, UHh + 1024, UHl + 1024, 1024, 1024, 2048);
        dim3 gW(1024 / 32, 512 / 32);
        transpose_split_kernel<<<gW, blk>>>(W_z, W0h, W0l,                                         512, 1024, 512);
        transpose_split_kernel<<<gW, blk>>>(W_h, W0h + (size_t)1024*512, W0l + (size_t)1024*512,   512, 1024, 512);
        int etotal4 = VOCAB * EDIM / 4;
        emb_split_kernel<<<(etotal4 + 255) / 256, 256>>>(emb, EMBh, EMBl, etotal4);
        bias_kernel<<<4, 256>>>(b_z, b_zl, b_zr, b_r, b_rl, b_rr, b_h, b_hl, b_hr);
    }

    // ---- level 0 ----
    {
        dim3 grid(2 * HDIM / BN, M0 / BM);
        gemm_mma_kernel<true><<<grid, 256, SMEM_BYTES>>>(EMBh, EMBl, tokens, W0h, W0l, BL0, PRE,
                                                         M0, 2 * HDIM, EDIM);
        int total4 = M0 * HDIM / 4;
        e0_kernel<<<(total4 + 255) / 256, 256>>>(PRE, HB0h, HB0l, total4);
    }

    // ---- tree levels: n = 512 -> 1 ----
    half* hph = HB0h; half* hpl = HB0l;
    int n = SEQ, lvl = 0;
    while (n > 1) {
        int Mn = BATCH * (n / 2);
        bool final = (n / 2 == 1);
        half* hoh = (lvl & 1) ? HB0h : HB1h;
        half* hol = (lvl & 1) ? HB0l : HB1l;
        int gy = (Mn + BM - 1) / BM;
        int total4 = Mn * HDIM / 4;

        // GEMM1: [hl|hr](Mn x 2048) @ UZR + [bz|br]
        {
            dim3 grid(2 * HDIM / BN, gy);
            gemm_mma_kernel<false><<<grid, 256, SMEM_BYTES>>>(hph, hpl, nullptr, UZRh, UZRl, BZR, PRE,
                                                              Mn, 2 * HDIM, 2 * HDIM);
        }
        e1_kernel<<<(total4 + 255) / 256, 256>>>(PRE, hph, hpl, ZB, RHh, RHl, total4);
        // GEMM2: [r*hl|r*hr](Mn x 2048) @ UH + bh
        {
            dim3 grid(HDIM / BN, gy);
            gemm_mma_kernel<false><<<grid, 256, SMEM_BYTES>>>(RHh, RHl, nullptr, UHh, UHl, BH, PRE,
                                                              Mn, HDIM, 2 * HDIM);
        }
        if (final)
            e2_kernel<true><<<(total4 + 255) / 256, 256>>>(PRE, ZB, hph, hpl, nullptr, nullptr,
                                                           (float*)d_out, total4);
        else
            e2_kernel<false><<<(total4 + 255) / 256, 256>>>(PRE, ZB, hph, hpl, hoh, hol,
                                                            nullptr, total4);

        hph = hoh; hpl = hol;
        n /= 2;
        lvl++;
    }
    (void)in_sizes; (void)n_in; (void)out_size;
}

// round 9
// speedup vs baseline: 1.2562x; 1.0465x over previous
#include <cuda_runtime.h>
#include <cuda_fp16.h>
#include <math.h>
#include <stdint.h>

// ---------------- problem constants ----------------
#define BATCH   64
#define SEQ     512
#define EDIM    512
#define HDIM    1024
#define VOCAB   32000
#define M0      (BATCH*SEQ)      // 32768 level-0 nodes

// ---------------- device scratch (allocation-free rule) ----------------
__device__ half  g_EMBh[(size_t)VOCAB * EDIM];
__device__ half  g_EMBl[(size_t)VOCAB * EDIM];
__device__ half  g_HB0h[(size_t)M0 * HDIM];
__device__ half  g_HB0l[(size_t)M0 * HDIM];
__device__ half  g_HB1h[(size_t)(M0/2) * HDIM];
__device__ half  g_HB1l[(size_t)(M0/2) * HDIM];
__device__ half  g_RHh [(size_t)(M0/2) * 2 * HDIM];
__device__ half  g_RHl [(size_t)(M0/2) * 2 * HDIM];
__device__ half  g_W0h [(size_t)(2*HDIM) * EDIM];      // [2048][512]  K-major
__device__ half  g_W0l [(size_t)(2*HDIM) * EDIM];
__device__ half  g_UZRh[(size_t)(2*HDIM) * (2*HDIM)];  // [2048][2048]
__device__ half  g_UZRl[(size_t)(2*HDIM) * (2*HDIM)];
__device__ half  g_UHh [(size_t)HDIM * (2*HDIM)];      // [1024][2048]
__device__ half  g_UHl [(size_t)HDIM * (2*HDIM)];
__device__ float g_PRE[(size_t)M0 * 2 * HDIM];
__device__ float g_Z  [(size_t)(M0/2) * HDIM];
__device__ float g_BL0[2*HDIM];
__device__ float g_BZR[2*HDIM];
__device__ float g_BH [HDIM];

// ================= helpers =================
__device__ __forceinline__ uint32_t smem_u32(const void* p) {
    uint32_t a;
    asm("{ .reg .u64 t; cvta.to.shared.u64 t, %1; cvt.u32.u64 %0, t; }" : "=r"(a) : "l"(p));
    return a;
}
__device__ __forceinline__ void split1(float v, half& h, half& l) {
    h = __float2half_rn(v);
    l = __float2half_rn(v - __half2float(h));
}
__device__ __forceinline__ float4 ld4h(const half* p) {
    uint2 u = *(const uint2*)p;
    __half2 a = *(__half2*)&u.x, b = *(__half2*)&u.y;
    float2 fa = __half22float2(a), fb = __half22float2(b);
    return make_float4(fa.x, fa.y, fb.x, fb.y);
}
__device__ __forceinline__ void st4split(half* ph, half* pl, float4 v) {
    half h0, l0, h1, l1, h2, l2, h3, l3;
    split1(v.x, h0, l0); split1(v.y, h1, l1);
    split1(v.z, h2, l2); split1(v.w, h3, l3);
    __half2 H0 = __halves2half2(h0, h1), H1 = __halves2half2(h2, h3);
    __half2 L0 = __halves2half2(l0, l1), L1 = __halves2half2(l2, l3);
    uint2 uh, ul;
    uh.x = *(uint32_t*)&H0; uh.y = *(uint32_t*)&H1;
    ul.x = *(uint32_t*)&L0; ul.y = *(uint32_t*)&L1;
    *(uint2*)ph = uh; *(uint2*)pl = ul;
}

#define CP16(dst, src) asm volatile("cp.async.cg.shared.global [%0], [%1], 16;" :: "r"(dst), "l"(src))
#define CP_COMMIT()    asm volatile("cp.async.commit_group;" ::: "memory")
#define CP_WAIT(n)     asm volatile("cp.async.wait_group %0;" :: "n"(n) : "memory")

#define LDSM4(r0, r1, r2, r3, addr)                                              \
    asm volatile("ldmatrix.sync.aligned.m8n8.x4.shared.b16 {%0,%1,%2,%3}, [%4];" \
        : "=r"(r0), "=r"(r1), "=r"(r2), "=r"(r3) : "r"(addr))

#define MMA16816(d, a, b0, b1)                                                   \
    asm volatile("mma.sync.aligned.m16n8k16.row.col.f32.f16.f16.f32 "            \
        "{%0,%1,%2,%3}, {%4,%5,%6,%7}, {%8,%9}, {%0,%1,%2,%3};"                  \
        : "+f"((d)[0]), "+f"((d)[1]), "+f"((d)[2]), "+f"((d)[3])                  \
        : "r"((a)[0]), "r"((a)[1]), "r"((a)[2]), "r"((a)[3]), "r"(b0), "r"(b1))

// ================= packing kernels =================
__global__ void transpose_split_kernel(const float* __restrict__ src,
                                       half* __restrict__ dh, half* __restrict__ dl,
                                       int R, int C, int dpitch)
{
    __shared__ float t[32][33];
    int c0 = blockIdx.x * 32, r0 = blockIdx.y * 32;
    int x = threadIdx.x, y = threadIdx.y;   // 32 x 8
    #pragma unroll
    for (int i = 0; i < 32; i += 8) {
        int r = r0 + y + i, c = c0 + x;
        t[y + i][x] = (r < R && c < C) ? src[(size_t)r * C + c] : 0.f;
    }
    __syncthreads();
    #pragma unroll
    for (int i = 0; i < 32; i += 8) {
        int c = c0 + y + i, r = r0 + x;
        if (c < C && r < R) {
            float v = t[x][y + i];
            half h, l; split1(v, h, l);
            dh[(size_t)c * dpitch + r] = h;
            dl[(size_t)c * dpitch + r] = l;
        }
    }
}

__global__ void emb_split_kernel(const float* __restrict__ emb,
                                 half* __restrict__ eh, half* __restrict__ el, int total4)
{
    int q = blockIdx.x * blockDim.x + threadIdx.x;
    if (q >= total4) return;
    int idx = q * 4;
    float4 v = *(const float4*)(emb + idx);
    st4split(eh + idx, el + idx, v);
}

__global__ void bias_kernel(
    const float* __restrict__ bz,  const float* __restrict__ bzl, const float* __restrict__ bzr,
    const float* __restrict__ br,  const float* __restrict__ brl, const float* __restrict__ brr,
    const float* __restrict__ bh,  const float* __restrict__ bhl, const float* __restrict__ bhr)
{
    int i = blockIdx.x * blockDim.x + threadIdx.x;
    if (i >= 1024) return;
    float bzs = bz[i] + bzl[i] + bzr[i];
    float brs = br[i] + brl[i] + brr[i];
    float bhs = bh[i] + bhl[i] + bhr[i];
    g_BZR[i] = bzs; g_BZR[1024 + i] = brs;
    g_BH[i]  = bhs;
    g_BL0[i] = bzs; g_BL0[1024 + i] = bhs;
}

// ================= fp16x3 mma GEMM, cp.async 3-stage, 128 threads =================
// C(MxN) = (Ah+Al)(MxK) @ (Bh+Bl)(NxK)^T + bias; drop Al*Bl.
// BM=64, BN=128, BK=32. 4 warps: 2m x 2n, warp tile 32x64.
// M % 64 == 0, N % 128 == 0, K % 32 == 0 guaranteed by problem shapes.
#define BM 64
#define BN 128
#define BK 32
#define PAD_B 80
#define OA_H 0
#define OA_L (64 * PAD_B)                 // 5120
#define OB_H (2 * 64 * PAD_B)             // 10240
#define OB_L (OB_H + 128 * PAD_B)         // 20480
#define STAGE_BYTES (OB_L + 128 * PAD_B)  // 30720
#define NSTAGE 3
#define SMEM_BYTES (NSTAGE * STAGE_BYTES) // 92160

template<bool GATHER>
__global__ void __launch_bounds__(128, 2)
gemm_mma_kernel(const half* __restrict__ Ah, const half* __restrict__ Al,
                const int* __restrict__ tok,
                const half* __restrict__ Bh, const half* __restrict__ Bl,
                const float* __restrict__ bias,
                float* __restrict__ C, int M, int N, int K)
{
    extern __shared__ char smem[];
    const uint32_t sb = smem_u32(smem);
    const int tid  = threadIdx.x;
    const int lane = tid & 31;
    const int wid  = tid >> 5;
    const int warp_m = wid & 1;          // 2 m-warps of 32 rows
    const int warp_n = wid >> 1;         // 2 n-warps of 64 cols
    const int bm = blockIdx.y * BM, bn = blockIdx.x * BN;

    // ---- cp.async mapping: 12 x 16B per thread per stage ----
    // planes: i 0-1 A_h rows r0,r0+32 ; 2-3 A_l ; 4-7 B_h rows r0..r0+96 ; 8-11 B_l
    const int r0  = tid >> 2;            // 0..31
    const int seg = (tid & 3) * 16;
    const char* srcp[12];
    uint32_t    dsto[12];
    #pragma unroll
    for (int i = 0; i < 12; i++) {
        if (i < 4) {
            int rl = r0 + 32 * (i & 1);
            int gr = bm + rl;
            size_t ar = GATHER ? (size_t)__ldg(&tok[gr]) : (size_t)gr;
            const half* base = (i < 2) ? Ah : Al;
            srcp[i] = (const char*)(base + ar * K) + seg;
            dsto[i] = ((i < 2) ? OA_H : OA_L) + (uint32_t)(rl * PAD_B + seg);
        } else {
            int j  = (i - 4) & 3;
            int rl = r0 + 32 * j;
            const half* base = (i < 8) ? Bh : Bl;
            srcp[i] = (const char*)(base + (size_t)(bn + rl) * K) + seg;
            dsto[i] = ((i < 8) ? OB_H : OB_L) + (uint32_t)(rl * PAD_B + seg);
        }
    }

    const int NT = K / BK;
    auto issue = [&](int kt) {
        if (kt < NT) {
            const uint32_t d = sb + (kt % NSTAGE) * STAGE_BYTES;
            const size_t g = (size_t)kt * 64;   // 32 halves = 64B per k-tile
            #pragma unroll
            for (int i = 0; i < 12; i++) CP16(d + dsto[i], srcp[i] + g);
        }
        CP_COMMIT();
    };

    // ---- ldmatrix lane addressing ----
    const uint32_t a_lane_off = (uint32_t)((warp_m * 32 + (lane & 15)) * PAD_B + ((lane >> 4) * 8) * 2);
    const uint32_t b_lane_off = (uint32_t)((warp_n * 64 + ((lane >> 4) << 3) + (lane & 7)) * PAD_B
                                           + (((lane >> 3) & 1) * 8) * 2);

    float acc[2][8][4];
    #pragma unroll
    for (int mt = 0; mt < 2; mt++)
        #pragma unroll
        for (int t = 0; t < 8; t++)
            #pragma unroll
            for (int j = 0; j < 4; j++) acc[mt][t][j] = 0.f;

    issue(0);
    issue(1);

    for (int kt = 0; kt < NT; kt++) {
        CP_WAIT(1);            // group kt complete (only kt+1 may be pending)
        __syncthreads();       // all warps done computing kt-1 -> slot (kt+2)%3 free
        issue(kt + 2);

        const uint32_t sbase = sb + (kt % NSTAGE) * STAGE_BYTES;
        #pragma unroll
        for (int ks = 0; ks < 2; ks++) {
            const uint32_t koff = ks * 32;  // 16 halves * 2B
            uint32_t ah[2][4], al[2][4], bh[4][4], bl[4][4];
            #pragma unroll
            for (int mt = 0; mt < 2; mt++) {
                uint32_t ad = sbase + a_lane_off + mt * (16 * PAD_B) + koff;
                LDSM4(ah[mt][0], ah[mt][1], ah[mt][2], ah[mt][3], ad + OA_H);
                LDSM4(al[mt][0], al[mt][1], al[mt][2], al[mt][3], ad + OA_L);
            }
            #pragma unroll
            for (int ng = 0; ng < 4; ng++) {
                uint32_t bd = sbase + b_lane_off + ng * (16 * PAD_B) + koff;
                LDSM4(bh[ng][0], bh[ng][1], bh[ng][2], bh[ng][3], bd + OB_H);
                LDSM4(bl[ng][0], bl[ng][1], bl[ng][2], bl[ng][3], bd + OB_L);
            }
            #pragma unroll
            for (int mt = 0; mt < 2; mt++)
                #pragma unroll
                for (int ng = 0; ng < 4; ng++)
                    #pragma unroll
                    for (int p = 0; p < 2; p++) {
                        float* c = acc[mt][ng * 2 + p];
                        MMA16816(c, ah[mt], bh[ng][2 * p], bh[ng][2 * p + 1]);
                        MMA16816(c, ah[mt], bl[ng][2 * p], bl[ng][2 * p + 1]);
                        MMA16816(c, al[mt], bh[ng][2 * p], bh[ng][2 * p + 1]);
                    }
        }
    }

    // ---- epilogue ----
    const int r0e = bm + warp_m * 32 + (lane >> 2);
    const int c0e = bn + warp_n * 64 + (lane & 3) * 2;
    #pragma unroll
    for (int mt = 0; mt < 2; mt++) {
        const int row = r0e + mt * 16;
        #pragma unroll
        for (int t = 0; t < 8; t++) {
            const int col = c0e + t * 8;
            const float b0 = bias[col], b1 = bias[col + 1];
            float2 v0 = make_float2(acc[mt][t][0] + b0, acc[mt][t][1] + b1);
            *(float2*)(C + (size_t)row * N + col) = v0;
            float2 v1 = make_float2(acc[mt][t][2] + b0, acc[mt][t][3] + b1);
            *(float2*)(C + (size_t)(row + 8) * N + col) = v1;
        }
    }
}

// ================= elementwise epilogues =================
__device__ __forceinline__ float sigmf(float x) { return 1.f / (1.f + expf(-x)); }

__global__ void e0_kernel(const float* __restrict__ pre,
                          half* __restrict__ hh, half* __restrict__ hl, int total4)
{
    int q = blockIdx.x * blockDim.x + threadIdx.x;
    if (q >= total4) return;
    int idx = q * 4;
    int m = idx >> 10, j = idx & 1023;
    size_t o = (size_t)m * 2048 + j;
    float4 zp = *(const float4*)(pre + o);
    float4 hp = *(const float4*)(pre + o + 1024);
    float4 r;
    r.x = (1.f - sigmf(zp.x)) * tanhf(hp.x);
    r.y = (1.f - sigmf(zp.y)) * tanhf(hp.y);
    r.z = (1.f - sigmf(zp.z)) * tanhf(hp.z);
    r.w = (1.f - sigmf(zp.w)) * tanhf(hp.w);
    st4split(hh + idx, hl + idx, r);
}

__global__ void e1_kernel(const float* __restrict__ pre,
                          const half* __restrict__ hph, const half* __restrict__ hpl,
                          float* __restrict__ zb,
                          half* __restrict__ rhh, half* __restrict__ rhl, int total4)
{
    int q = blockIdx.x * blockDim.x + threadIdx.x;
    if (q >= total4) return;
    int idx = q * 4;
    int m = idx >> 10, j = idx & 1023;
    size_t o = (size_t)m * 2048 + j;
    float4 zp = *(const float4*)(pre + o);
    float4 rp = *(const float4*)(pre + o + 1024);
    float4 Hh = ld4h(hph + o),        Lh = ld4h(hpl + o);
    float4 Hr = ld4h(hph + o + 1024), Lr = ld4h(hpl + o + 1024);
    float hlx = Hh.x + Lh.x, hly = Hh.y + Lh.y, hlz = Hh.z + Lh.z, hlw = Hh.w + Lh.w;
    float hrx = Hr.x + Lr.x, hry = Hr.y + Lr.y, hrz = Hr.z + Lr.z, hrw = Hr.w + Lr.w;
    float4 z;
    z.x = sigmf(zp.x); z.y = sigmf(zp.y); z.z = sigmf(zp.z); z.w = sigmf(zp.w);
    float rx = sigmf(rp.x), ry = sigmf(rp.y), rz = sigmf(rp.z), rw = sigmf(rp.w);
    *(float4*)(zb + idx) = z;
    st4split(rhh + o,        rhl + o,        make_float4(rx * hlx, ry * hly, rz * hlz, rw * hlw));
    st4split(rhh + o + 1024, rhl + o + 1024, make_float4(rx * hrx, ry * hry, rz * hrz, rw * hrw));
}

template<bool FINAL>
__global__ void e2_kernel(const float* __restrict__ pre2, const float* __restrict__ zb,
                          const half* __restrict__ hph, const half* __restrict__ hpl,
                          half* __restrict__ hoh, half* __restrict__ hol,
                          float* __restrict__ outf, int total4)
{
    int q = blockIdx.x * blockDim.x + threadIdx.x;
    if (q >= total4) return;
    int idx = q * 4;
    int m = idx >> 10, j = idx & 1023;
    size_t o = (size_t)m * 2048 + j;
    float4 z  = *(const float4*)(zb + idx);
    float4 p  = *(const float4*)(pre2 + idx);
    float4 Hh = ld4h(hph + o),        Lh = ld4h(hpl + o);
    float4 Hr = ld4h(hph + o + 1024), Lr = ld4h(hpl + o + 1024);
    float4 r;
    r.x = z.x * ((Hh.x + Lh.x) + (Hr.x + Lr.x)) + (1.f - z.x) * tanhf(p.x);
    r.y = z.y * ((Hh.y + Lh.y) + (Hr.y + Lr.y)) + (1.f - z.y) * tanhf(p.y);
    r.z = z.z * ((Hh.z + Lh.z) + (Hr.z + Lr.z)) + (1.f - z.z) * tanhf(p.z);
    r.w = z.w * ((Hh.w + Lh.w) + (Hr.w + Lr.w)) + (1.f - z.w) * tanhf(p.w);
    if (FINAL) *(float4*)(outf + idx) = r;
    else       st4split(hoh + idx, hol + idx, r);
}

// ================= launch =================
extern "C" void kernel_launch(void* const* d_in, const int* in_sizes, int n_in,
                              void* d_out, int out_size)
{
    const int*   tokens = (const int*)  d_in[0];
    const float* emb    = (const float*)d_in[1];
    const float* W_z  = (const float*)d_in[2];
    const float* b_z  = (const float*)d_in[3];
    const float* U_zl = (const float*)d_in[4];
    const float* b_zl = (const float*)d_in[5];
    const float* U_zr = (const float*)d_in[6];
    const float* b_zr = (const float*)d_in[7];
    const float* W_r  = (const float*)d_in[8];
    const float* b_r  = (const float*)d_in[9];
    const float* U_rl = (const float*)d_in[10];
    const float* b_rl = (const float*)d_in[11];
    const float* U_rr = (const float*)d_in[12];
    const float* b_rr = (const float*)d_in[13];
    const float* W_h  = (const float*)d_in[14];
    const float* b_h  = (const float*)d_in[15];
    const float* U_hl = (const float*)d_in[16];
    const float* b_hl = (const float*)d_in[17];
    const float* U_hr = (const float*)d_in[18];
    const float* b_hr = (const float*)d_in[19];
    (void)W_r; // level-0 r is multiplied by hl=hr=0

    half *EMBh, *EMBl, *HB0h, *HB0l, *HB1h, *HB1l, *RHh, *RHl;
    half *W0h, *W0l, *UZRh, *UZRl, *UHh, *UHl;
    float *PRE, *ZB, *BL0, *BZR, *BH;
    cudaGetSymbolAddress((void**)&EMBh, g_EMBh);
    cudaGetSymbolAddress((void**)&EMBl, g_EMBl);
    cudaGetSymbolAddress((void**)&HB0h, g_HB0h);
    cudaGetSymbolAddress((void**)&HB0l, g_HB0l);
    cudaGetSymbolAddress((void**)&HB1h, g_HB1h);
    cudaGetSymbolAddress((void**)&HB1l, g_HB1l);
    cudaGetSymbolAddress((void**)&RHh,  g_RHh);
    cudaGetSymbolAddress((void**)&RHl,  g_RHl);
    cudaGetSymbolAddress((void**)&W0h,  g_W0h);
    cudaGetSymbolAddress((void**)&W0l,  g_W0l);
    cudaGetSymbolAddress((void**)&UZRh, g_UZRh);
    cudaGetSymbolAddress((void**)&UZRl, g_UZRl);
    cudaGetSymbolAddress((void**)&UHh,  g_UHh);
    cudaGetSymbolAddress((void**)&UHl,  g_UHl);
    cudaGetSymbolAddress((void**)&PRE,  g_PRE);
    cudaGetSymbolAddress((void**)&ZB,   g_Z);
    cudaGetSymbolAddress((void**)&BL0,  g_BL0);
    cudaGetSymbolAddress((void**)&BZR,  g_BZR);
    cudaGetSymbolAddress((void**)&BH,   g_BH);

    cudaFuncSetAttribute(gemm_mma_kernel<true>,
                         cudaFuncAttributeMaxDynamicSharedMemorySize, SMEM_BYTES);
    cudaFuncSetAttribute(gemm_mma_kernel<false>,
                         cudaFuncAttributeMaxDynamicSharedMemorySize, SMEM_BYTES);

    // ---- pack: transpose+split weights into [N][K] hi/lo half planes ----
    {
        dim3 blk(32, 8);
        dim3 g32(1024 / 32, 1024 / 32);
        transpose_split_kernel<<<g32, blk>>>(U_zl, UZRh, UZRl,                                 1024, 1024, 2048);
        transpose_split_kernel<<<g32, blk>>>(U_rl, UZRh + (size_t)1024*2048, UZRl + (size_t)1024*2048, 1024, 1024, 2048);
        transpose_split_kernel<<<g32, blk>>>(U_zr, UZRh + 1024, UZRl + 1024,                   1024, 1024, 2048);
        transpose_split_kernel<<<g32, blk>>>(U_rr, UZRh + (size_t)1024*2048 + 1024, UZRl + (size_t)1024*2048 + 1024, 1024, 1024, 2048);
        transpose_split_kernel<<<g32, blk>>>(U_hl, UHh, UHl,               1024, 1024, 2048);
        transpose_split_kernel<<<g32, blk>>>(U_hr, UHh + 1024, UHl + 1024, 1024, 1024, 2048);
        dim3 gW(1024 / 32, 512 / 32);
        transpose_split_kernel<<<gW, blk>>>(W_z, W0h, W0l,                                         512, 1024, 512);
        transpose_split_kernel<<<gW, blk>>>(W_h, W0h + (size_t)1024*512, W0l + (size_t)1024*512,   512, 1024, 512);
        int etotal4 = VOCAB * EDIM / 4;
        emb_split_kernel<<<(etotal4 + 255) / 256, 256>>>(emb, EMBh, EMBl, etotal4);
        bias_kernel<<<4, 256>>>(b_z, b_zl, b_zr, b_r, b_rl, b_rr, b_h, b_hl, b_hr);
    }

    // ---- level 0 ----
    {
        dim3 grid(2 * HDIM / BN, M0 / BM);
        gemm_mma_kernel<true><<<grid, 128, SMEM_BYTES>>>(EMBh, EMBl, tokens, W0h, W0l, BL0, PRE,
                                                         M0, 2 * HDIM, EDIM);
        int total4 = M0 * HDIM / 4;
        e0_kernel<<<(total4 + 255) / 256, 256>>>(PRE, HB0h, HB0l, total4);
    }

    // ---- tree levels: n = 512 -> 1 ----
    half* hph = HB0h; half* hpl = HB0l;
    int n = SEQ, lvl = 0;
    while (n > 1) {
        int Mn = BATCH * (n / 2);
        bool final = (n / 2 == 1);
        half* hoh = (lvl & 1) ? HB0h : HB1h;
        half* hol = (lvl & 1) ? HB0l : HB1l;
        int gy = Mn / BM;
        int total4 = Mn * HDIM / 4;

        // GEMM1: [hl|hr](Mn x 2048) @ UZR + [bz|br]
        {
            dim3 grid(2 * HDIM / BN, gy);
            gemm_mma_kernel<false><<<grid, 128, SMEM_BYTES>>>(hph, hpl, nullptr, UZRh, UZRl, BZR, PRE,
                                                              Mn, 2 * HDIM, 2 * HDIM);
        }
        e1_kernel<<<(total4 + 255) / 256, 256>>>(PRE, hph, hpl, ZB, RHh, RHl, total4);
        // GEMM2: [r*hl|r*hr](Mn x 2048) @ UH + bh
        {
            dim3 grid(HDIM / BN, gy);
            gemm_mma_kernel<false><<<grid, 128, SMEM_BYTES>>>(RHh, RHl, nullptr, UHh, UHl, BH, PRE,
                                                              Mn, HDIM, 2 * HDIM);
        }
        if (final)
            e2_kernel<true><<<(total4 + 255) / 256, 256>>>(PRE, ZB, hph, hpl, nullptr, nullptr,
                                                           (float*)d_out, total4);
        else
            e2_kernel<false><<<(total4 + 255) / 256, 256>>>(PRE, ZB, hph, hpl, hoh, hol,
                                                            nullptr, total4);

        hph = hoh; hpl = hol;
        n /= 2;
        lvl++;
    }
    (void)in_sizes; (void)n_in; (void)out_size;
}